// round 16
// baseline (speedup 1.0000x reference)
#include <cuda_runtime.h>
#include <cuda_bf16.h>
#include <math_constants.h>
#include <cstdint>

#define B_  16
#define C_  256
#define IC_ 32
#define M_  16384
#define TM2 256
#define TILES2 (M_/TM2)            // 64
#define RSQRT_IC 0.17677669529663687f

// ---------------- scratch (__device__ globals; no allocation allowed) -------
// g stored as pre-split bf16 hi/lo in k3 A-fragment order:
//   per (b,tile,warp): [ks(2)][mf(2)][lane(32)][e(4)] uint32  (512 words/warp)
__device__ __align__(16) uint32_t d_gfh[(size_t)B_*TILES2*8*512];   // 16.7 MB
__device__ __align__(16) uint32_t d_gfl[(size_t)B_*TILES2*8*512];   // 16.7 MB
__device__ float d_partG[(size_t)B_*TILES2*IC_*IC_];   // per-tile t.t^T (4 MB)
__device__ float d_partS[(size_t)B_*TILES2*IC_];       // per-tile sum(t)
__device__ float d_attn[(size_t)B_*IC_*IC_];           // softmax result
// k1 weights packed in mma.m16n8k16 B-fragment order (N=32 each)
__device__ __align__(16) unsigned short d_Bt [32*256];
__device__ __align__(16) unsigned short d_Bgh[32*256];
__device__ __align__(16) unsigned short d_Bgl[32*256];
// k3 weff packed per batch in B-fragment order (N=256, K=32), bf16 hi/lo
__device__ __align__(16) unsigned short d_WH[(size_t)B_*8192];
__device__ __align__(16) unsigned short d_WL[(size_t)B_*8192];

// ---------------- helpers ----------------------------------------------------
__device__ __forceinline__ uint32_t smem_u32(const void* p) {
    uint32_t a;
    asm("{ .reg .u64 t; cvta.to.shared.u64 t, %1; cvt.u32.u64 %0, t; }" : "=r"(a) : "l"(p));
    return a;
}
#define CP_ASYNC16(dst, src) \
    asm volatile("cp.async.ca.shared.global [%0], [%1], 16;" :: "r"(dst), "l"(src))
#define CP_COMMIT() asm volatile("cp.async.commit_group;" ::: "memory")
#define CP_WAIT(n)  asm volatile("cp.async.wait_group %0;" :: "n"(n) : "memory")

// ---- packed fp32 (Blackwell FFMA2)
__device__ __forceinline__ unsigned long long pk2(float a, float b) {
    unsigned long long r;
    asm("mov.b64 %0, {%1, %2};" : "=l"(r) : "f"(a), "f"(b));
    return r;
}
__device__ __forceinline__ void upk2(float& a, float& b, unsigned long long r) {
    asm("mov.b64 {%0, %1}, %2;" : "=f"(a), "=f"(b) : "l"(r));
}
__device__ __forceinline__ void ffma2(unsigned long long& d,
                                      unsigned long long a, unsigned long long b) {
    asm("fma.rn.f32x2 %0, %1, %2, %0;" : "+l"(d) : "l"(a), "l"(b));
}

__device__ __forceinline__ void mma_bf16(float* d, const uint32_t* a,
                                         uint32_t b0, uint32_t b1) {
    asm volatile(
        "mma.sync.aligned.m16n8k16.row.col.f32.bf16.bf16.f32 "
        "{%0,%1,%2,%3}, {%4,%5,%6,%7}, {%8,%9}, {%0,%1,%2,%3};"
        : "+f"(d[0]), "+f"(d[1]), "+f"(d[2]), "+f"(d[3])
        : "r"(a[0]), "r"(a[1]), "r"(a[2]), "r"(a[3]), "r"(b0), "r"(b1));
}

__device__ __forceinline__ void split_pack(float f0, float f1,
                                           uint32_t& hi, uint32_t& lo, uint32_t& rn) {
    uint32_t b0 = __float_as_uint(f0), b1 = __float_as_uint(f1);
    hi = __byte_perm(b0, b1, 0x7632);                 // trunc {hi16(f0), hi16(f1)}
    float l0 = f0 - __uint_as_float(b0 & 0xFFFF0000u);
    float l1 = f1 - __uint_as_float(b1 & 0xFFFF0000u);
    __nv_bfloat162 p = __floats2bfloat162_rn(l0, l1);
    lo = *reinterpret_cast<uint32_t*>(&p);
    __nv_bfloat162 q = __floats2bfloat162_rn(f0, f1);  // rn single for theta
    rn = *reinterpret_cast<uint32_t*>(&q);
}
__device__ __forceinline__ void splitg(float f0, float f1,
                                       uint32_t& hi, uint32_t& lo) {
    uint32_t b0 = __float_as_uint(f0), b1 = __float_as_uint(f1);
    hi = __byte_perm(b0, b1, 0x7632);
    float l0 = f0 - __uint_as_float(b0 & 0xFFFF0000u);
    float l1 = f1 - __uint_as_float(b1 & 0xFFFF0000u);
    __nv_bfloat162 p = __floats2bfloat162_rn(l0, l1);
    lo = *reinterpret_cast<uint32_t*>(&p);
}

// swizzled smem read: buffer is 16 channels x 32 floats, 16B units XORed by ch
__device__ __forceinline__ float ldsx(const float* buf, int ch, int m) {
    return buf[ch * 32 + ((((m >> 2) ^ (ch & 7)) << 2) | (m & 3))];
}

// ============================================================================
// k0: pack k1 weights into N=32 B-fragment layouts.
// ============================================================================
__global__ void k0_prep(const float* __restrict__ g_w, const float* __restrict__ theta_w)
{
    int idx = blockIdx.x * 256 + threadIdx.x;    // 0..16383
    int n = idx >> 8, k = idx & 255;             // n 0..63
    int ks = k >> 4, kr = k & 15;
    int r = kr >> 3, ct = (kr & 7) >> 1, e = kr & 1;
    int nb = (n & 31) >> 3, lane = (n & 7) * 4 + ct;
    int us = ((((ks * 4 + nb) * 32 + lane) * 2 + r) << 1) | e;

    if (n < 32) {
        float wv = theta_w[n * C_ + k];
        d_Bt[us] = __bfloat16_as_ushort(__float2bfloat16(wv));   // rn
    } else {
        float wv = g_w[(n - 32) * C_ + k];
        uint32_t bits = __float_as_uint(wv);
        float hif = __uint_as_float(bits & 0xFFFF0000u);
        d_Bgh[us] = (unsigned short)(bits >> 16);                // trunc hi
        d_Bgl[us] = __bfloat16_as_ushort(__float2bfloat16(wv - hif));
    }
}

// ============================================================================
// k1: per (batch, 256-pixel tile): D[256 m][64 n] = X^T @ [theta;g]^T
//   theta -> Gram partials; g -> pre-split bf16 hi/lo fragment words (coalesced)
// ============================================================================
__global__ __launch_bounds__(256, 2) void k1_proj(
    const float* __restrict__ x,
    const float* __restrict__ g_b, const float* __restrict__ theta_b)
{
    __shared__ __align__(16) float Xs[8][3][16 * 32];
    float* Ts = &Xs[0][0][0];                         // [256][36] after main loop

    const int t = threadIdx.x;
    const int w = t >> 5, lane = t & 31;
    const int gr = lane >> 2, ct = lane & 3;
    const int tile = blockIdx.x, b = blockIdx.y;
    const int mbase = tile * TM2;

    const float* xw = x + (size_t)b * C_ * M_ + mbase + 32 * w;
    const int srow = lane >> 3;
    const int sseg = lane & 7;
    const uint32_t swb = smem_u32(&Xs[w][0][0]);

    float acc[16][4];
#pragma unroll
    for (int i = 0; i < 16; i++)
#pragma unroll
        for (int j = 0; j < 4; j++) acc[i][j] = 0.f;

    const uint2* Bt2  = (const uint2*)d_Bt;
    const uint2* Bgh2 = (const uint2*)d_Bgh;
    const uint2* Bgl2 = (const uint2*)d_Bgl;

#pragma unroll
    for (int pc = 0; pc < 2; pc++) {
        uint32_t dst = swb + (uint32_t)pc * 2048;
#pragma unroll
        for (int kk = 0; kk < 4; kk++) {
            int row = srow + kk * 4;
            CP_ASYNC16(dst + (uint32_t)(row * 128 + ((sseg ^ (row & 7)) << 4)),
                       xw + (size_t)(pc * 16 + row) * M_ + sseg * 4);
        }
        CP_COMMIT();
    }

#pragma unroll
    for (int ck = 0; ck < 16; ck++) {
        if (ck <= 14) { CP_WAIT(1); } else { CP_WAIT(0); }
        __syncwarp();

        const float* Xb = &Xs[w][ck % 3][0];
        const int kb = 2 * ct;

        uint2 bt[4], bh[4], bl[4];
#pragma unroll
        for (int nb = 0; nb < 4; nb++) {
            bt[nb] = __ldg(&Bt2 [(ck * 4 + nb) * 32 + lane]);
            bh[nb] = __ldg(&Bgh2[(ck * 4 + nb) * 32 + lane]);
            bl[nb] = __ldg(&Bgl2[(ck * 4 + nb) * 32 + lane]);
        }

#pragma unroll
        for (int mf = 0; mf < 2; mf++) {
            const int mo = mf * 16;
            float f00 = ldsx(Xb, kb + 0, gr + mo),      f01 = ldsx(Xb, kb + 1, gr + mo);
            float f10 = ldsx(Xb, kb + 0, gr + 8 + mo),  f11 = ldsx(Xb, kb + 1, gr + 8 + mo);
            float f20 = ldsx(Xb, kb + 8, gr + mo),      f21 = ldsx(Xb, kb + 9, gr + mo);
            float f30 = ldsx(Xb, kb + 8, gr + 8 + mo),  f31 = ldsx(Xb, kb + 9, gr + 8 + mo);
            uint32_t ahi[4], alo[4], arn[4];
            split_pack(f00, f01, ahi[0], alo[0], arn[0]);
            split_pack(f10, f11, ahi[1], alo[1], arn[1]);
            split_pack(f20, f21, ahi[2], alo[2], arn[2]);
            split_pack(f30, f31, ahi[3], alo[3], arn[3]);
#pragma unroll
            for (int nb = 0; nb < 4; nb++) {
                mma_bf16(acc[mf * 4 + nb],     arn, bt[nb].x, bt[nb].y);   // theta
                mma_bf16(acc[8 + mf * 4 + nb], ahi, bh[nb].x, bh[nb].y);   // g hh
                mma_bf16(acc[8 + mf * 4 + nb], ahi, bl[nb].x, bl[nb].y);   // g hl
                mma_bf16(acc[8 + mf * 4 + nb], alo, bh[nb].x, bh[nb].y);   // g lh
            }
        }

        if (ck + 2 < 16) {
            uint32_t dst = swb + (uint32_t)((ck + 2) % 3) * 2048;
#pragma unroll
            for (int kk = 0; kk < 4; kk++) {
                int row = srow + kk * 4;
                CP_ASYNC16(dst + (uint32_t)(row * 128 + ((sseg ^ (row & 7)) << 4)),
                           xw + (size_t)((ck + 2) * 16 + row) * M_ + sseg * 4);
            }
            CP_COMMIT();
        }
    }

    // ---- g -> fragment-packed bf16 hi/lo (coalesced STG.128)
    {
        uint32_t* FH = d_gfh + ((size_t)(b * TILES2 + tile) * 8 + w) * 512;
        uint32_t* FL = d_gfl + ((size_t)(b * TILES2 + tile) * 8 + w) * 512;
#pragma unroll
        for (int ks = 0; ks < 2; ks++) {
            int nA = 2 * ks * 8 + 2 * ct, nB = (2 * ks + 1) * 8 + 2 * ct;
            float bA0 = __ldg(&g_b[nA]), bA1 = __ldg(&g_b[nA + 1]);
            float bB0 = __ldg(&g_b[nB]), bB1 = __ldg(&g_b[nB + 1]);
#pragma unroll
            for (int mf = 0; mf < 2; mf++) {
                const float* aA = acc[8 + mf * 4 + 2 * ks];
                const float* aB = acc[8 + mf * 4 + 2 * ks + 1];
                uint32_t h0, l0, h1, l1, h2, l2, h3, l3;
                splitg(aA[0] + bA0, aA[1] + bA1, h0, l0);
                splitg(aA[2] + bA0, aA[3] + bA1, h1, l1);
                splitg(aB[0] + bB0, aB[1] + bB1, h2, l2);
                splitg(aB[2] + bB0, aB[3] + bB1, h3, l3);
                int off = ((ks * 2 + mf) * 32 + lane) * 4;
                *(uint4*)(FH + off) = make_uint4(h0, h1, h2, h3);
                *(uint4*)(FL + off) = make_uint4(l0, l1, l2, l3);
            }
        }
    }

    __syncthreads();

    // ---- theta -> Ts[256][36]
#pragma unroll
    for (int mf = 0; mf < 2; mf++) {
#pragma unroll
        for (int nb = 0; nb < 4; nb++) {
            int n = nb * 8 + 2 * ct;
            int mloc = 32 * w + mf * 16 + gr;
            float tb0 = __ldg(&theta_b[n]), tb1 = __ldg(&theta_b[n + 1]);
            const float* a = acc[mf * 4 + nb];
            Ts[mloc * 36 + n]           = a[0] + tb0;
            Ts[mloc * 36 + n + 1]       = a[1] + tb1;
            Ts[(mloc + 8) * 36 + n]     = a[2] + tb0;
            Ts[(mloc + 8) * 36 + n + 1] = a[3] + tb1;
        }
    }
    __syncthreads();

    // ---- partial Gram (FFMA2)
    {
        const int j = lane;
        unsigned long long gac2[2] = {0ull, 0ull};
        float sac = 0.f;
#pragma unroll 4
        for (int m = 0; m < TM2; m++) {
            float4 tr = *(const float4*)(Ts + m * 36 + w * 4);
            float tj = Ts[m * 36 + j];
            unsigned long long tjp = pk2(tj, tj);
            ffma2(gac2[0], pk2(tr.x, tr.y), tjp);
            ffma2(gac2[1], pk2(tr.z, tr.w), tjp);
            if (w == 0) sac += tj;
        }
        float gac[4];
        upk2(gac[0], gac[1], gac2[0]);
        upk2(gac[2], gac[3], gac2[1]);
        float* pG = d_partG + (size_t)(b * TILES2 + tile) * IC_ * IC_;
#pragma unroll
        for (int ii = 0; ii < 4; ii++)
            pG[(w * 4 + ii) * IC_ + j] = gac[ii];
        if (w == 0)
            d_partS[(size_t)(b * TILES2 + tile) * IC_ + j] = sac;
    }
}

// ============================================================================
// k2: full reduce over 64 tiles, sigma, softmax -> d_attn  (one block/batch)
// ============================================================================
__global__ __launch_bounds__(256) void k2_attn()
{
    __shared__ float gram[IC_ * IC_];
    __shared__ float mu[IC_];
    const int t = threadIdx.x, b = blockIdx.x;

    for (int e = t; e < IC_ * IC_; e += 256) {
        float s = 0.f;
        const float* p = d_partG + (size_t)b * TILES2 * IC_ * IC_ + e;
#pragma unroll 8
        for (int tl = 0; tl < TILES2; tl++) s += p[(size_t)tl * IC_ * IC_];
        gram[e] = s;
    }
    if (t < IC_) {
        float s = 0.f;
        const float* p = d_partS + (size_t)b * TILES2 * IC_ + t;
#pragma unroll 8
        for (int tl = 0; tl < TILES2; tl++) s += p[tl * IC_];
        mu[t] = s * (1.0f / M_);
    }
    __syncthreads();

    if (t < IC_) {
        float row[IC_];
        float mx = -CUDART_INF_F;
#pragma unroll
        for (int jj = 0; jj < IC_; jj++) {
            float v = (gram[t * IC_ + jj] * (1.0f / M_) - mu[t] * mu[jj]) * RSQRT_IC;
            row[jj] = v; mx = fmaxf(mx, v);
        }
        float sum = 0.f;
#pragma unroll
        for (int jj = 0; jj < IC_; jj++) { row[jj] = __expf(row[jj] - mx); sum += row[jj]; }
        float inv = 1.0f / sum;
#pragma unroll
        for (int jj = 0; jj < IC_; jj++)
            d_attn[(size_t)b * IC_ * IC_ + t * IC_ + jj] = row[jj] * inv;
    }
}

// ============================================================================
// k4: weff[j][c] = sum_i w_w[c][i] * attn[i][j]; pack hi/lo into B-fragment
//   layout for k3's mma (N=256 -> nb=c>>3, K=32 -> ks=j>>4).
// ============================================================================
__global__ __launch_bounds__(128) void k4_weff(const float* __restrict__ w_w)
{
    __shared__ float attn[IC_ * IC_];
    const int t = threadIdx.x, cb = blockIdx.x, b = blockIdx.y;

    for (int e = t; e < IC_ * IC_; e += 128)
        attn[e] = d_attn[(size_t)b * IC_ * IC_ + e];
    __syncthreads();

    const int c = cb * 128 + t;
    float ww[IC_];
#pragma unroll
    for (int ii = 0; ii < IC_; ii += 4) {
        float4 v = __ldg((const float4*)(w_w + c * IC_ + ii));
        ww[ii] = v.x; ww[ii+1] = v.y; ww[ii+2] = v.z; ww[ii+3] = v.w;
    }
    unsigned short* WH = d_WH + (size_t)b * 8192;
    unsigned short* WL = d_WL + (size_t)b * 8192;
    const int nb = c >> 3;
#pragma unroll
    for (int jj = 0; jj < IC_; jj++) {
        float s = 0.f;
#pragma unroll
        for (int ii = 0; ii < IC_; ii++) s += ww[ii] * attn[ii * IC_ + jj];
        uint32_t bits = __float_as_uint(s);
        float hif = __uint_as_float(bits & 0xFFFF0000u);
        int kr = jj & 15;
        int r = kr >> 3, ct = (kr & 7) >> 1, e = kr & 1, ks = jj >> 4;
        int lane = (c & 7) * 4 + ct;
        int idx = ((((ks * 32 + nb) * 32 + lane) * 2 + r) << 1) | e;
        WH[idx] = (unsigned short)(bits >> 16);
        WL[idx] = __bfloat16_as_ushort(__float2bfloat16(s - hif));
    }
}

// ============================================================================
// k3: out[b][c][m] = sum_j weff[j][c]*g[j][m] + w_b[c] + x[b][c][m]
//   mma.sync v3: A-fragments loaded directly (coalesced) from k1's packed
//   hi/lo fragment words -> no staging phase, no block barriers. 3 CTAs/SM.
// ============================================================================
__global__ __launch_bounds__(256, 3) void k3_out(
    const float* __restrict__ x, const float* __restrict__ w_b,
    float* __restrict__ out)
{
    __shared__ __align__(16) float sbuf[9216];        // 8 warp tiles [32 c][36 m]

    const int t = threadIdx.x;
    const int tile = blockIdx.x, b = blockIdx.y;
    const int mbase = tile * 256;

    const int w = t >> 5, lane = t & 31;
    const int ct = lane & 3;
    const int mw = 32 * w;

    // ---- A fragments: direct coalesced loads of k1's packed hi/lo words
    uint32_t ahi[2][2][4], alo[2][2][4];
    {
        const uint4* FH = (const uint4*)(d_gfh + ((size_t)(b * TILES2 + tile) * 8 + w) * 512);
        const uint4* FL = (const uint4*)(d_gfl + ((size_t)(b * TILES2 + tile) * 8 + w) * 512);
#pragma unroll
        for (int ks = 0; ks < 2; ks++)
#pragma unroll
            for (int mf = 0; mf < 2; mf++) {
                uint4 h = __ldg(&FH[(ks * 2 + mf) * 32 + lane]);
                uint4 l = __ldg(&FL[(ks * 2 + mf) * 32 + lane]);
                ahi[ks][mf][0] = h.x; ahi[ks][mf][1] = h.y;
                ahi[ks][mf][2] = h.z; ahi[ks][mf][3] = h.w;
                alo[ks][mf][0] = l.x; alo[ks][mf][1] = l.y;
                alo[ks][mf][2] = l.z; alo[ks][mf][3] = l.w;
            }
    }

    float* epi = sbuf + w * 1152;                      // [32 c][36 m] per warp
    const uint2* WH2 = (const uint2*)(d_WH + (size_t)b * 8192);
    const uint2* WL2 = (const uint2*)(d_WL + (size_t)b * 8192);
    const int s = lane & 7, rbase = lane >> 3;

    for (int gIdx = 0; gIdx < 8; gIdx++) {
        float acc[4][2][4];
#pragma unroll
        for (int i = 0; i < 4; i++)
#pragma unroll
            for (int j = 0; j < 2; j++)
#pragma unroll
                for (int q = 0; q < 4; q++) acc[i][j][q] = 0.f;

#pragma unroll
        for (int nl = 0; nl < 4; nl++) {
            int nb = gIdx * 4 + nl;
#pragma unroll
            for (int ks = 0; ks < 2; ks++) {
                uint2 bh = __ldg(&WH2[(ks * 32 + nb) * 32 + lane]);
                uint2 bl = __ldg(&WL2[(ks * 32 + nb) * 32 + lane]);
#pragma unroll
                for (int mf = 0; mf < 2; mf++) {
                    mma_bf16(acc[nl][mf], ahi[ks][mf], bh.x, bh.y);   // hh
                    mma_bf16(acc[nl][mf], ahi[ks][mf], bl.x, bl.y);   // hl
                    mma_bf16(acc[nl][mf], alo[ks][mf], bh.x, bh.y);   // lh
                }
            }
        }

        // ---- scatter fragments into warp-private tile (conflict-free)
        __syncwarp();
        {
            const int gr = lane >> 2;
#pragma unroll
            for (int nl = 0; nl < 4; nl++) {
                int cl = nl * 8 + 2 * ct;
#pragma unroll
                for (int mf = 0; mf < 2; mf++) {
                    int m = mf * 16 + gr;
                    epi[cl * 36 + m]           = acc[nl][mf][0];
                    epi[(cl + 1) * 36 + m]     = acc[nl][mf][1];
                    epi[cl * 36 + m + 8]       = acc[nl][mf][2];
                    epi[(cl + 1) * 36 + m + 8] = acc[nl][mf][3];
                }
            }
        }
        __syncwarp();

        // ---- coalesced epilogue: 8 passes x (4 rows x 128B)
#pragma unroll
        for (int p = 0; p < 8; p++) {
            int rl = p * 4 + rbase;                    // c_local 0..31
            int c = gIdx * 32 + rl;
            float4 a = *(const float4*)(epi + rl * 36 + s * 4);
            size_t gi = ((size_t)b * C_ + c) * M_ + mbase + mw + s * 4;
            float4 xv = *(const float4*)(x + gi);
            float wb = __ldg(&w_b[c]);
            float4 o = make_float4(a.x + wb + xv.x, a.y + wb + xv.y,
                                   a.z + wb + xv.z, a.w + wb + xv.w);
            *(float4*)(out + gi) = o;
        }
        __syncwarp();
    }
}

// ============================================================================
extern "C" void kernel_launch(void* const* d_in, const int* in_sizes, int n_in,
                              void* d_out, int out_size)
{
    const float* x       = (const float*)d_in[0];
    const float* g_w     = (const float*)d_in[1];
    const float* g_b     = (const float*)d_in[2];
    const float* theta_w = (const float*)d_in[3];
    const float* theta_b = (const float*)d_in[4];
    const float* w_w     = (const float*)d_in[5];
    const float* w_b     = (const float*)d_in[6];
    float* out = (float*)d_out;

    k0_prep<<<64, 256>>>(g_w, theta_w);
    k1_proj<<<dim3(TILES2, B_), 256>>>(x, g_b, theta_b);
    k2_attn<<<B_, 256>>>();
    k4_weff<<<dim3(2, B_), 128>>>(w_w);
    k3_out<<<dim3(M_ / 256, B_), 256>>>(x, w_b, out);
}

// round 17
// speedup vs baseline: 1.1127x; 1.1127x over previous
#include <cuda_runtime.h>
#include <cuda_bf16.h>
#include <math_constants.h>
#include <cstdint>

#define B_  16
#define C_  256
#define IC_ 32
#define M_  16384
#define TM2 256
#define TILES2 (M_/TM2)            // 64
#define RSQRT_IC 0.17677669529663687f

// ---------------- scratch (__device__ globals; no allocation allowed) -------
// g stored as pre-split bf16 hi/lo in k3 A-fragment order:
//   per (b,tile,warp): [ks(2)][mf(2)][lane(32)][e(4)] uint32  (512 words/warp)
__device__ __align__(16) uint32_t d_gfh[(size_t)B_*TILES2*8*512];   // 16.7 MB
__device__ __align__(16) uint32_t d_gfl[(size_t)B_*TILES2*8*512];   // 16.7 MB
__device__ float d_partG[(size_t)B_*TILES2*IC_*IC_];   // per-tile t.t^T (4 MB)
__device__ float d_partS[(size_t)B_*TILES2*IC_];       // per-tile sum(t)
__device__ float d_partG2[(size_t)B_*8*IC_*IC_];       // stage-2 partials
__device__ float d_partS2[(size_t)B_*8*IC_];
__device__ float d_attn[(size_t)B_*IC_*IC_];           // softmax result
// k1 weights packed in mma.m16n8k16 B-fragment order (N=32 each)
__device__ __align__(16) unsigned short d_Bt [32*256];
__device__ __align__(16) unsigned short d_Bgh[32*256];
__device__ __align__(16) unsigned short d_Bgl[32*256];
// k3 weff packed per batch in B-fragment order (N=256, K=32), bf16 hi/lo
__device__ __align__(16) unsigned short d_WH[(size_t)B_*8192];
__device__ __align__(16) unsigned short d_WL[(size_t)B_*8192];

// ---------------- helpers ----------------------------------------------------
__device__ __forceinline__ uint32_t smem_u32(const void* p) {
    uint32_t a;
    asm("{ .reg .u64 t; cvta.to.shared.u64 t, %1; cvt.u32.u64 %0, t; }" : "=r"(a) : "l"(p));
    return a;
}
#define CP_ASYNC16(dst, src) \
    asm volatile("cp.async.ca.shared.global [%0], [%1], 16;" :: "r"(dst), "l"(src))
#define CP_COMMIT() asm volatile("cp.async.commit_group;" ::: "memory")
#define CP_WAIT(n)  asm volatile("cp.async.wait_group %0;" :: "n"(n) : "memory")

// ---- packed fp32 (Blackwell FFMA2)
__device__ __forceinline__ unsigned long long pk2(float a, float b) {
    unsigned long long r;
    asm("mov.b64 %0, {%1, %2};" : "=l"(r) : "f"(a), "f"(b));
    return r;
}
__device__ __forceinline__ void upk2(float& a, float& b, unsigned long long r) {
    asm("mov.b64 {%0, %1}, %2;" : "=f"(a), "=f"(b) : "l"(r));
}
__device__ __forceinline__ void ffma2(unsigned long long& d,
                                      unsigned long long a, unsigned long long b) {
    asm("fma.rn.f32x2 %0, %1, %2, %0;" : "+l"(d) : "l"(a), "l"(b));
}

__device__ __forceinline__ void mma_bf16(float* d, const uint32_t* a,
                                         uint32_t b0, uint32_t b1) {
    asm volatile(
        "mma.sync.aligned.m16n8k16.row.col.f32.bf16.bf16.f32 "
        "{%0,%1,%2,%3}, {%4,%5,%6,%7}, {%8,%9}, {%0,%1,%2,%3};"
        : "+f"(d[0]), "+f"(d[1]), "+f"(d[2]), "+f"(d[3])
        : "r"(a[0]), "r"(a[1]), "r"(a[2]), "r"(a[3]), "r"(b0), "r"(b1));
}

__device__ __forceinline__ void split_pack(float f0, float f1,
                                           uint32_t& hi, uint32_t& lo, uint32_t& rn) {
    uint32_t b0 = __float_as_uint(f0), b1 = __float_as_uint(f1);
    hi = __byte_perm(b0, b1, 0x7632);                 // trunc {hi16(f0), hi16(f1)}
    float l0 = f0 - __uint_as_float(b0 & 0xFFFF0000u);
    float l1 = f1 - __uint_as_float(b1 & 0xFFFF0000u);
    __nv_bfloat162 p = __floats2bfloat162_rn(l0, l1);
    lo = *reinterpret_cast<uint32_t*>(&p);
    __nv_bfloat162 q = __floats2bfloat162_rn(f0, f1);  // rn single for theta
    rn = *reinterpret_cast<uint32_t*>(&q);
}
__device__ __forceinline__ void splitg(float f0, float f1,
                                       uint32_t& hi, uint32_t& lo) {
    uint32_t b0 = __float_as_uint(f0), b1 = __float_as_uint(f1);
    hi = __byte_perm(b0, b1, 0x7632);
    float l0 = f0 - __uint_as_float(b0 & 0xFFFF0000u);
    float l1 = f1 - __uint_as_float(b1 & 0xFFFF0000u);
    __nv_bfloat162 p = __floats2bfloat162_rn(l0, l1);
    lo = *reinterpret_cast<uint32_t*>(&p);
}

// swizzled smem read: buffer is 16 channels x 32 floats, 16B units XORed by ch
__device__ __forceinline__ float ldsx(const float* buf, int ch, int m) {
    return buf[ch * 32 + ((((m >> 2) ^ (ch & 7)) << 2) | (m & 3))];
}

// ============================================================================
// k0: pack k1 weights into N=32 B-fragment layouts.
// ============================================================================
__global__ void k0_prep(const float* __restrict__ g_w, const float* __restrict__ theta_w)
{
    int idx = blockIdx.x * 256 + threadIdx.x;    // 0..16383
    int n = idx >> 8, k = idx & 255;             // n 0..63
    int ks = k >> 4, kr = k & 15;
    int r = kr >> 3, ct = (kr & 7) >> 1, e = kr & 1;
    int nb = (n & 31) >> 3, lane = (n & 7) * 4 + ct;
    int us = ((((ks * 4 + nb) * 32 + lane) * 2 + r) << 1) | e;

    if (n < 32) {
        float wv = theta_w[n * C_ + k];
        d_Bt[us] = __bfloat16_as_ushort(__float2bfloat16(wv));   // rn
    } else {
        float wv = g_w[(n - 32) * C_ + k];
        uint32_t bits = __float_as_uint(wv);
        float hif = __uint_as_float(bits & 0xFFFF0000u);
        d_Bgh[us] = (unsigned short)(bits >> 16);                // trunc hi
        d_Bgl[us] = __bfloat16_as_ushort(__float2bfloat16(wv - hif));
    }
}

// ============================================================================
// k1: per (batch, 256-pixel tile): D[256 m][64 n] = X^T @ [theta;g]^T
//   theta -> Gram partials; g -> pre-split bf16 hi/lo fragment words (coalesced)
// ============================================================================
__global__ __launch_bounds__(256, 2) void k1_proj(
    const float* __restrict__ x,
    const float* __restrict__ g_b, const float* __restrict__ theta_b)
{
    __shared__ __align__(16) float Xs[8][3][16 * 32];
    float* Ts = &Xs[0][0][0];                         // [256][36] after main loop

    const int t = threadIdx.x;
    const int w = t >> 5, lane = t & 31;
    const int gr = lane >> 2, ct = lane & 3;
    const int tile = blockIdx.x, b = blockIdx.y;
    const int mbase = tile * TM2;

    const float* xw = x + (size_t)b * C_ * M_ + mbase + 32 * w;
    const int srow = lane >> 3;
    const int sseg = lane & 7;
    const uint32_t swb = smem_u32(&Xs[w][0][0]);

    float acc[16][4];
#pragma unroll
    for (int i = 0; i < 16; i++)
#pragma unroll
        for (int j = 0; j < 4; j++) acc[i][j] = 0.f;

    const uint2* Bt2  = (const uint2*)d_Bt;
    const uint2* Bgh2 = (const uint2*)d_Bgh;
    const uint2* Bgl2 = (const uint2*)d_Bgl;

#pragma unroll
    for (int pc = 0; pc < 2; pc++) {
        uint32_t dst = swb + (uint32_t)pc * 2048;
#pragma unroll
        for (int kk = 0; kk < 4; kk++) {
            int row = srow + kk * 4;
            CP_ASYNC16(dst + (uint32_t)(row * 128 + ((sseg ^ (row & 7)) << 4)),
                       xw + (size_t)(pc * 16 + row) * M_ + sseg * 4);
        }
        CP_COMMIT();
    }

#pragma unroll
    for (int ck = 0; ck < 16; ck++) {
        if (ck <= 14) { CP_WAIT(1); } else { CP_WAIT(0); }
        __syncwarp();

        const float* Xb = &Xs[w][ck % 3][0];
        const int kb = 2 * ct;

        uint2 bt[4], bh[4], bl[4];
#pragma unroll
        for (int nb = 0; nb < 4; nb++) {
            bt[nb] = __ldg(&Bt2 [(ck * 4 + nb) * 32 + lane]);
            bh[nb] = __ldg(&Bgh2[(ck * 4 + nb) * 32 + lane]);
            bl[nb] = __ldg(&Bgl2[(ck * 4 + nb) * 32 + lane]);
        }

#pragma unroll
        for (int mf = 0; mf < 2; mf++) {
            const int mo = mf * 16;
            float f00 = ldsx(Xb, kb + 0, gr + mo),      f01 = ldsx(Xb, kb + 1, gr + mo);
            float f10 = ldsx(Xb, kb + 0, gr + 8 + mo),  f11 = ldsx(Xb, kb + 1, gr + 8 + mo);
            float f20 = ldsx(Xb, kb + 8, gr + mo),      f21 = ldsx(Xb, kb + 9, gr + mo);
            float f30 = ldsx(Xb, kb + 8, gr + 8 + mo),  f31 = ldsx(Xb, kb + 9, gr + 8 + mo);
            uint32_t ahi[4], alo[4], arn[4];
            split_pack(f00, f01, ahi[0], alo[0], arn[0]);
            split_pack(f10, f11, ahi[1], alo[1], arn[1]);
            split_pack(f20, f21, ahi[2], alo[2], arn[2]);
            split_pack(f30, f31, ahi[3], alo[3], arn[3]);
#pragma unroll
            for (int nb = 0; nb < 4; nb++) {
                mma_bf16(acc[mf * 4 + nb],     arn, bt[nb].x, bt[nb].y);   // theta
                mma_bf16(acc[8 + mf * 4 + nb], ahi, bh[nb].x, bh[nb].y);   // g hh
                mma_bf16(acc[8 + mf * 4 + nb], ahi, bl[nb].x, bl[nb].y);   // g hl
                mma_bf16(acc[8 + mf * 4 + nb], alo, bh[nb].x, bh[nb].y);   // g lh
            }
        }

        if (ck + 2 < 16) {
            uint32_t dst = swb + (uint32_t)((ck + 2) % 3) * 2048;
#pragma unroll
            for (int kk = 0; kk < 4; kk++) {
                int row = srow + kk * 4;
                CP_ASYNC16(dst + (uint32_t)(row * 128 + ((sseg ^ (row & 7)) << 4)),
                           xw + (size_t)((ck + 2) * 16 + row) * M_ + sseg * 4);
            }
            CP_COMMIT();
        }
    }

    // ---- g -> fragment-packed bf16 hi/lo (coalesced STG.128)
    {
        uint32_t* FH = d_gfh + ((size_t)(b * TILES2 + tile) * 8 + w) * 512;
        uint32_t* FL = d_gfl + ((size_t)(b * TILES2 + tile) * 8 + w) * 512;
#pragma unroll
        for (int ks = 0; ks < 2; ks++) {
            int nA = 2 * ks * 8 + 2 * ct, nB = (2 * ks + 1) * 8 + 2 * ct;
            float bA0 = __ldg(&g_b[nA]), bA1 = __ldg(&g_b[nA + 1]);
            float bB0 = __ldg(&g_b[nB]), bB1 = __ldg(&g_b[nB + 1]);
#pragma unroll
            for (int mf = 0; mf < 2; mf++) {
                const float* aA = acc[8 + mf * 4 + 2 * ks];
                const float* aB = acc[8 + mf * 4 + 2 * ks + 1];
                uint32_t h0, l0, h1, l1, h2, l2, h3, l3;
                splitg(aA[0] + bA0, aA[1] + bA1, h0, l0);
                splitg(aA[2] + bA0, aA[3] + bA1, h1, l1);
                splitg(aB[0] + bB0, aB[1] + bB1, h2, l2);
                splitg(aB[2] + bB0, aB[3] + bB1, h3, l3);
                int off = ((ks * 2 + mf) * 32 + lane) * 4;
                *(uint4*)(FH + off) = make_uint4(h0, h1, h2, h3);
                *(uint4*)(FL + off) = make_uint4(l0, l1, l2, l3);
            }
        }
    }

    __syncthreads();

    // ---- theta -> Ts[256][36]
#pragma unroll
    for (int mf = 0; mf < 2; mf++) {
#pragma unroll
        for (int nb = 0; nb < 4; nb++) {
            int n = nb * 8 + 2 * ct;
            int mloc = 32 * w + mf * 16 + gr;
            float tb0 = __ldg(&theta_b[n]), tb1 = __ldg(&theta_b[n + 1]);
            const float* a = acc[mf * 4 + nb];
            Ts[mloc * 36 + n]           = a[0] + tb0;
            Ts[mloc * 36 + n + 1]       = a[1] + tb1;
            Ts[(mloc + 8) * 36 + n]     = a[2] + tb0;
            Ts[(mloc + 8) * 36 + n + 1] = a[3] + tb1;
        }
    }
    __syncthreads();

    // ---- partial Gram (FFMA2)
    {
        const int j = lane;
        unsigned long long gac2[2] = {0ull, 0ull};
        float sac = 0.f;
#pragma unroll 4
        for (int m = 0; m < TM2; m++) {
            float4 tr = *(const float4*)(Ts + m * 36 + w * 4);
            float tj = Ts[m * 36 + j];
            unsigned long long tjp = pk2(tj, tj);
            ffma2(gac2[0], pk2(tr.x, tr.y), tjp);
            ffma2(gac2[1], pk2(tr.z, tr.w), tjp);
            if (w == 0) sac += tj;
        }
        float gac[4];
        upk2(gac[0], gac[1], gac2[0]);
        upk2(gac[2], gac[3], gac2[1]);
        float* pG = d_partG + (size_t)(b * TILES2 + tile) * IC_ * IC_;
#pragma unroll
        for (int ii = 0; ii < 4; ii++)
            pG[(w * 4 + ii) * IC_ + j] = gac[ii];
        if (w == 0)
            d_partS[(size_t)(b * TILES2 + tile) * IC_ + j] = sac;
    }
}

// ============================================================================
// k2a: stage-1 reduction of Gram partials
// ============================================================================
__global__ __launch_bounds__(256) void k2a_reduce()
{
    const int seg = blockIdx.x, b = blockIdx.y, t = threadIdx.x;
    const float* p = d_partG + (size_t)(b * TILES2 + seg * 8) * IC_ * IC_;
#pragma unroll
    for (int e = t; e < IC_ * IC_; e += 256) {
        float s = 0.f;
#pragma unroll
        for (int tl = 0; tl < 8; tl++) s += p[(size_t)tl * IC_ * IC_ + e];
        d_partG2[(size_t)(b * 8 + seg) * IC_ * IC_ + e] = s;
    }
    if (t < IC_) {
        const float* q = d_partS + (size_t)(b * TILES2 + seg * 8) * IC_;
        float s = 0.f;
#pragma unroll
        for (int tl = 0; tl < 8; tl++) s += q[tl * IC_ + t];
        d_partS2[(size_t)(b * 8 + seg) * IC_ + t] = s;
    }
}

// ============================================================================
// k2b: final reduce, sigma, softmax -> d_attn
// ============================================================================
__global__ __launch_bounds__(256) void k2_attn()
{
    __shared__ float gram[IC_ * IC_];
    __shared__ float mu[IC_];
    const int t = threadIdx.x, b = blockIdx.x;

    for (int e = t; e < IC_ * IC_; e += 256) {
        float s = 0.f;
        const float* p = d_partG2 + (size_t)b * 8 * IC_ * IC_ + e;
#pragma unroll
        for (int tl = 0; tl < 8; tl++) s += p[(size_t)tl * IC_ * IC_];
        gram[e] = s;
    }
    if (t < IC_) {
        float s = 0.f;
        const float* p = d_partS2 + (size_t)b * 8 * IC_ + t;
#pragma unroll
        for (int tl = 0; tl < 8; tl++) s += p[tl * IC_];
        mu[t] = s * (1.0f / M_);
    }
    __syncthreads();

    if (t < IC_) {
        float row[IC_];
        float mx = -CUDART_INF_F;
#pragma unroll
        for (int jj = 0; jj < IC_; jj++) {
            float v = (gram[t * IC_ + jj] * (1.0f / M_) - mu[t] * mu[jj]) * RSQRT_IC;
            row[jj] = v; mx = fmaxf(mx, v);
        }
        float sum = 0.f;
#pragma unroll
        for (int jj = 0; jj < IC_; jj++) { row[jj] = __expf(row[jj] - mx); sum += row[jj]; }
        float inv = 1.0f / sum;
#pragma unroll
        for (int jj = 0; jj < IC_; jj++)
            d_attn[(size_t)b * IC_ * IC_ + t * IC_ + jj] = row[jj] * inv;
    }
}

// ============================================================================
// k4: weff[j][c] = sum_i w_w[c][i] * attn[i][j]; pack hi/lo into B-fragment
//   layout. 256 threads: thread = (c = cb*128 + (t&127), jj-half = t>>7).
// ============================================================================
__global__ __launch_bounds__(256) void k4_weff(const float* __restrict__ w_w)
{
    __shared__ float attn[IC_ * IC_];
    const int t = threadIdx.x, cb = blockIdx.x, b = blockIdx.y;

    for (int e = t; e < IC_ * IC_; e += 256)
        attn[e] = d_attn[(size_t)b * IC_ * IC_ + e];
    __syncthreads();

    const int c = cb * 128 + (t & 127);
    const int jh = t >> 7;                        // 0 or 1: jj 0..15 / 16..31
    float ww[IC_];
#pragma unroll
    for (int ii = 0; ii < IC_; ii += 4) {
        float4 v = __ldg((const float4*)(w_w + c * IC_ + ii));
        ww[ii] = v.x; ww[ii+1] = v.y; ww[ii+2] = v.z; ww[ii+3] = v.w;
    }
    unsigned short* WH = d_WH + (size_t)b * 8192;
    unsigned short* WL = d_WL + (size_t)b * 8192;
    const int nb = c >> 3;
#pragma unroll
    for (int jl = 0; jl < 16; jl++) {
        int jj = jh * 16 + jl;
        float s = 0.f;
#pragma unroll
        for (int ii = 0; ii < IC_; ii++) s += ww[ii] * attn[ii * IC_ + jj];
        uint32_t bits = __float_as_uint(s);
        float hif = __uint_as_float(bits & 0xFFFF0000u);
        int kr = jj & 15;
        int r = kr >> 3, ct = (kr & 7) >> 1, e = kr & 1, ks = jj >> 4;
        int lane = (c & 7) * 4 + ct;
        int idx = ((((ks * 32 + nb) * 32 + lane) * 2 + r) << 1) | e;
        WH[idx] = (unsigned short)(bits >> 16);
        WL[idx] = __bfloat16_as_ushort(__float2bfloat16(s - hif));
    }
}

// ============================================================================
// k3: out[b][c][m] = sum_j weff[j][c]*g[j][m] + w_b[c] + x[b][c][m]
//   mma.sync v3 (round-15, measured good): direct coalesced A-fragment loads,
//   no staging phase, no block barriers; 2 CTAs/SM.
// ============================================================================
__global__ __launch_bounds__(256, 2) void k3_out(
    const float* __restrict__ x, const float* __restrict__ w_b,
    float* __restrict__ out)
{
    __shared__ __align__(16) float sbuf[9216];        // 8 warp tiles [32 c][36 m]

    const int t = threadIdx.x;
    const int tile = blockIdx.x, b = blockIdx.y;
    const int mbase = tile * 256;

    const int w = t >> 5, lane = t & 31;
    const int ct = lane & 3;
    const int mw = 32 * w;

    // ---- A fragments: direct coalesced loads of k1's packed hi/lo words
    uint32_t ahi[2][2][4], alo[2][2][4];
    {
        const uint4* FH = (const uint4*)(d_gfh + ((size_t)(b * TILES2 + tile) * 8 + w) * 512);
        const uint4* FL = (const uint4*)(d_gfl + ((size_t)(b * TILES2 + tile) * 8 + w) * 512);
#pragma unroll
        for (int ks = 0; ks < 2; ks++)
#pragma unroll
            for (int mf = 0; mf < 2; mf++) {
                uint4 h = __ldg(&FH[(ks * 2 + mf) * 32 + lane]);
                uint4 l = __ldg(&FL[(ks * 2 + mf) * 32 + lane]);
                ahi[ks][mf][0] = h.x; ahi[ks][mf][1] = h.y;
                ahi[ks][mf][2] = h.z; ahi[ks][mf][3] = h.w;
                alo[ks][mf][0] = l.x; alo[ks][mf][1] = l.y;
                alo[ks][mf][2] = l.z; alo[ks][mf][3] = l.w;
            }
    }

    float* epi = sbuf + w * 1152;                      // [32 c][36 m] per warp
    const uint2* WH2 = (const uint2*)(d_WH + (size_t)b * 8192);
    const uint2* WL2 = (const uint2*)(d_WL + (size_t)b * 8192);
    const int s = lane & 7, rbase = lane >> 3;

    for (int gIdx = 0; gIdx < 8; gIdx++) {
        float acc[4][2][4];
#pragma unroll
        for (int i = 0; i < 4; i++)
#pragma unroll
            for (int j = 0; j < 2; j++)
#pragma unroll
                for (int q = 0; q < 4; q++) acc[i][j][q] = 0.f;

#pragma unroll
        for (int nl = 0; nl < 4; nl++) {
            int nb = gIdx * 4 + nl;
#pragma unroll
            for (int ks = 0; ks < 2; ks++) {
                uint2 bh = __ldg(&WH2[(ks * 32 + nb) * 32 + lane]);
                uint2 bl = __ldg(&WL2[(ks * 32 + nb) * 32 + lane]);
#pragma unroll
                for (int mf = 0; mf < 2; mf++) {
                    mma_bf16(acc[nl][mf], ahi[ks][mf], bh.x, bh.y);   // hh
                    mma_bf16(acc[nl][mf], ahi[ks][mf], bl.x, bl.y);   // hl
                    mma_bf16(acc[nl][mf], alo[ks][mf], bh.x, bh.y);   // lh
                }
            }
        }

        // ---- scatter fragments into warp-private tile (conflict-free)
        __syncwarp();
        {
            const int gr = lane >> 2;
#pragma unroll
            for (int nl = 0; nl < 4; nl++) {
                int cl = nl * 8 + 2 * ct;
#pragma unroll
                for (int mf = 0; mf < 2; mf++) {
                    int m = mf * 16 + gr;
                    epi[cl * 36 + m]           = acc[nl][mf][0];
                    epi[(cl + 1) * 36 + m]     = acc[nl][mf][1];
                    epi[cl * 36 + m + 8]       = acc[nl][mf][2];
                    epi[(cl + 1) * 36 + m + 8] = acc[nl][mf][3];
                }
            }
        }
        __syncwarp();

        // ---- coalesced epilogue: 8 passes x (4 rows x 128B)
#pragma unroll
        for (int p = 0; p < 8; p++) {
            int rl = p * 4 + rbase;                    // c_local 0..31
            int c = gIdx * 32 + rl;
            float4 a = *(const float4*)(epi + rl * 36 + s * 4);
            size_t gi = ((size_t)b * C_ + c) * M_ + mbase + mw + s * 4;
            float4 xv = *(const float4*)(x + gi);
            float wb = __ldg(&w_b[c]);
            float4 o = make_float4(a.x + wb + xv.x, a.y + wb + xv.y,
                                   a.z + wb + xv.z, a.w + wb + xv.w);
            *(float4*)(out + gi) = o;
        }
        __syncwarp();
    }
}

// ============================================================================
extern "C" void kernel_launch(void* const* d_in, const int* in_sizes, int n_in,
                              void* d_out, int out_size)
{
    const float* x       = (const float*)d_in[0];
    const float* g_w     = (const float*)d_in[1];
    const float* g_b     = (const float*)d_in[2];
    const float* theta_w = (const float*)d_in[3];
    const float* theta_b = (const float*)d_in[4];
    const float* w_w     = (const float*)d_in[5];
    const float* w_b     = (const float*)d_in[6];
    float* out = (float*)d_out;

    k0_prep<<<64, 256>>>(g_w, theta_w);
    k1_proj<<<dim3(TILES2, B_), 256>>>(x, g_b, theta_b);
    k2a_reduce<<<dim3(8, B_), 256>>>();
    k2_attn<<<B_, 256>>>();
    k4_weff<<<dim3(2, B_), 256>>>(w_w);
    k3_out<<<dim3(M_ / 256, B_), 256>>>(x, w_b, out);
}